// round 9
// baseline (speedup 1.0000x reference)
#include <cuda_runtime.h>
#include <cstddef>

// Problem constants
#define H      1024
#define BSZ    4
#define TLEN   1024
#define G4H    4096          // 4*H
#define NTOK   4096          // BSZ*TLEN
#define VOCAB  32000

// Recurrent kernel config
#define NCTA_R 128
#define TPB_R  256
#define UPC    8             // hidden units per CTA (H / NCTA_R)
#define RPC    32            // gate rows per CTA (4*UPC)
#define WPAD   1028          // padded row stride for Whh slice in smem

// Scratch (device globals; no allocations allowed)
__device__ float g_act[(size_t)NTOK * H];
__device__ float g_pre[(size_t)NTOK * G4H];
__device__ float g_hs0[(size_t)NTOK * H];
__device__ float g_hs1[(size_t)NTOK * H];
__device__ float g_h[2 * BSZ * H];          // double-buffered by step parity
__device__ int g_slots[NCTA_R * 32];        // per-CTA mailbox, 128B apart; reset to 0
__device__ int g_flag;                      // master-published step token; reset to 0

// ---------------------------------------------------------------------------
// Packed fp32x2 helpers (FFMA2)
// ---------------------------------------------------------------------------
__device__ __forceinline__ unsigned long long pk2(float x, float y) {
    unsigned long long r;
    asm("mov.b64 %0, {%1, %2};" : "=l"(r) : "f"(x), "f"(y));
    return r;
}
__device__ __forceinline__ void ffma2(unsigned long long& d,
                                      unsigned long long a,
                                      unsigned long long b) {
    asm("fma.rn.f32x2 %0, %1, %2, %0;" : "+l"(d) : "l"(a), "l"(b));
}
__device__ __forceinline__ float2 upk2(unsigned long long v) {
    float2 f;
    asm("mov.b64 {%0, %1}, %2;" : "=f"(f.x), "=f"(f.y) : "l"(v));
    return f;
}

// ---------------------------------------------------------------------------
// Embedding gather: out[n, :] = emb[x[n], :]
// ---------------------------------------------------------------------------
__global__ void embed_kernel(const int* __restrict__ x,
                             const float* __restrict__ emb,
                             float* __restrict__ out)
{
    int n = blockIdx.x;
    int tok = __ldg(&x[n]);
    const float4* src = (const float4*)(emb + (size_t)tok * H);
    float4* dst = (float4*)(out + (size_t)n * H);
    dst[threadIdx.x] = __ldg(&src[threadIdx.x]);
}

// ---------------------------------------------------------------------------
// SGEMM: C[M,N] = A[M,K] * B[N,K]^T + bias1[N] (+ bias2[N])   (R6 version)
// ---------------------------------------------------------------------------
__global__ __launch_bounds__(256, 2)
void sgemm_abt(const float* __restrict__ A, const float* __restrict__ B,
               const float* __restrict__ bias1, const float* __restrict__ bias2,
               float* __restrict__ C, int M, int N, int K)
{
    __shared__ float As[16][132];
    __shared__ float Bs[16][132];
    const int tid = threadIdx.x;
    const int bm = blockIdx.y * 128;
    const int bn = blockIdx.x * 128;
    const int tx = tid & 15;
    const int ty = tid >> 4;
    const int lr = tid >> 2;          // 0..63
    const int lk = (tid & 3) << 2;    // 0,4,8,12

    const float* Ag = A + (size_t)(bm + lr) * K + lk;
    const float* Bg = B + (size_t)(bn + lr) * K + lk;

    unsigned long long acc2[4][8];
#pragma unroll
    for (int i = 0; i < 4; i++)
#pragma unroll
        for (int j = 0; j < 8; j++) acc2[i][j] = 0ull;

    float4 a0 = *(const float4*)(Ag);
    float4 a1 = *(const float4*)(Ag + (size_t)64 * K);
    float4 b0 = *(const float4*)(Bg);
    float4 b1 = *(const float4*)(Bg + (size_t)64 * K);

    for (int k0 = 0; k0 < K; k0 += 16) {
        __syncthreads();
        As[lk+0][lr]    = a0.x; As[lk+1][lr]    = a0.y; As[lk+2][lr]    = a0.z; As[lk+3][lr]    = a0.w;
        As[lk+0][lr+64] = a1.x; As[lk+1][lr+64] = a1.y; As[lk+2][lr+64] = a1.z; As[lk+3][lr+64] = a1.w;
        Bs[lk+0][lr]    = b0.x; Bs[lk+1][lr]    = b0.y; Bs[lk+2][lr]    = b0.z; Bs[lk+3][lr]    = b0.w;
        Bs[lk+0][lr+64] = b1.x; Bs[lk+1][lr+64] = b1.y; Bs[lk+2][lr+64] = b1.z; Bs[lk+3][lr+64] = b1.w;
        __syncthreads();
        if (k0 + 16 < K) {
            a0 = *(const float4*)(Ag + k0 + 16);
            a1 = *(const float4*)(Ag + (size_t)64 * K + k0 + 16);
            b0 = *(const float4*)(Bg + k0 + 16);
            b1 = *(const float4*)(Bg + (size_t)64 * K + k0 + 16);
        }
#pragma unroll
        for (int k = 0; k < 16; k++) {
            float4 aA = *(const float4*)&As[k][ty * 4];
            float4 aB = *(const float4*)&As[k][64 + ty * 4];
            float4 bA = *(const float4*)&Bs[k][tx * 4];
            float4 bB = *(const float4*)&Bs[k][64 + tx * 4];
            unsigned long long av2[4];
            av2[0] = pk2(aA.x, aA.y);
            av2[1] = pk2(aA.z, aA.w);
            av2[2] = pk2(aB.x, aB.y);
            av2[3] = pk2(aB.z, aB.w);
            unsigned long long bv2[8];
            bv2[0] = pk2(bA.x, bA.x);
            bv2[1] = pk2(bA.y, bA.y);
            bv2[2] = pk2(bA.z, bA.z);
            bv2[3] = pk2(bA.w, bA.w);
            bv2[4] = pk2(bB.x, bB.x);
            bv2[5] = pk2(bB.y, bB.y);
            bv2[6] = pk2(bB.z, bB.z);
            bv2[7] = pk2(bB.w, bB.w);
#pragma unroll
            for (int i = 0; i < 4; i++)
#pragma unroll
                for (int j = 0; j < 8; j++)
                    ffma2(acc2[i][j], av2[i], bv2[j]);
        }
    }

    float acc[8][8];
#pragma unroll
    for (int i2 = 0; i2 < 4; i2++)
#pragma unroll
        for (int j = 0; j < 8; j++) {
            float2 v = upk2(acc2[i2][j]);
            acc[2 * i2][j]     = v.x;
            acc[2 * i2 + 1][j] = v.y;
        }

    float bb[8];
#pragma unroll
    for (int jh = 0; jh < 2; jh++)
#pragma unroll
        for (int j = 0; j < 4; j++) {
            int n = bn + jh * 64 + tx * 4 + j;
            float v = bias1 ? __ldg(&bias1[n]) : 0.f;
            if (bias2) v += __ldg(&bias2[n]);
            bb[jh * 4 + j] = v;
        }
#pragma unroll
    for (int ih = 0; ih < 2; ih++)
#pragma unroll
        for (int i = 0; i < 4; i++) {
            int m = bm + ih * 64 + ty * 4 + i;
#pragma unroll
            for (int jh = 0; jh < 2; jh++) {
                float4 v;
                v.x = acc[ih*4+i][jh*4+0] + bb[jh*4+0];
                v.y = acc[ih*4+i][jh*4+1] + bb[jh*4+1];
                v.z = acc[ih*4+i][jh*4+2] + bb[jh*4+2];
                v.w = acc[ih*4+i][jh*4+3] + bb[jh*4+3];
                *(float4*)&C[(size_t)m * N + bn + jh * 64 + tx * 4] = v;
            }
        }
}

// ---------------------------------------------------------------------------
// Persistent LSTM recurrence. 128 resident CTAs, Whh slice pinned in SMEM.
// Grid barrier: atomic-free mailbox. Each CTA release-stores token t+1 into
// its own slot (128B apart). CTA 0's 128 threads acquire-poll all slots in
// parallel (one L2 RT, not 128 serialized RMWs), sync, publish flag; other
// CTAs acquire-poll flag >= t+1. Monotonic tokens (no per-step resets);
// exit round zeroes slots+flag -> deterministic graph replays.
// g_h double-buffered by step parity (fixes WAR race between fast/slow CTAs).
// ---------------------------------------------------------------------------
__global__ __launch_bounds__(TPB_R)
void lstm_recurrent(const float* __restrict__ pre,
                    const float* __restrict__ Whh,
                    float* __restrict__ hs)
{
    extern __shared__ float sm[];
    float* whh_s = sm;                       // RPC * WPAD
    float* h_s   = sm + RPC * WPAD;          // BSZ * H
    float* z_s   = h_s + BSZ * H;            // RPC * BSZ
    float* c_s   = z_s + RPC * BSZ;          // 32

    const int tid  = threadIdx.x;
    const int cta  = blockIdx.x;
    const int warp = tid >> 5;
    const int lane = tid & 31;

    for (int i = tid; i < RPC * H; i += TPB_R) {
        int r = i >> 10;
        int k = i & (H - 1);
        int q = r >> 3;
        int uu = r & 7;
        int grow = q * H + cta * UPC + uu;
        whh_s[r * WPAD + k] = __ldg(&Whh[(size_t)grow * H + k]);
    }
    if (tid < 32) c_s[tid] = 0.f;
    __syncthreads();

    for (int t = 0; t < TLEN; t++) {
        // h(t-1) into smem (zeros at t=0); read parity buffer (t-1)&1
        float4* hs4 = (float4*)h_s;
        if (t == 0) {
            for (int i = tid; i < (BSZ * H) / 4; i += TPB_R)
                hs4[i] = make_float4(0.f, 0.f, 0.f, 0.f);
        } else {
            const float4* hg = (const float4*)(g_h + ((t - 1) & 1) * BSZ * H);
            for (int i = tid; i < (BSZ * H) / 4; i += TPB_R)
                hs4[i] = __ldcg(hg + i);
        }
        // prefetch pre-activations for gate threads
        float p0 = 0.f, p1 = 0.f, p2 = 0.f, p3 = 0.f;
        int uu = 0, b = 0;
        if (tid < 32) {
            uu = tid >> 2; b = tid & 3;
            size_t base = ((size_t)(b * TLEN + t)) * G4H + cta * UPC + uu;
            p0 = __ldg(&pre[base]);
            p1 = __ldg(&pre[base + H]);
            p2 = __ldg(&pre[base + 2 * H]);
            p3 = __ldg(&pre[base + 3 * H]);
        }
        __syncthreads();

        // z[r][b] = sum_k Whh_s[r][k] * h[b][k]; warp owns 4 rows, all 4 b.
        float acc[4][4];
#pragma unroll
        for (int i = 0; i < 4; i++)
#pragma unroll
            for (int j = 0; j < 4; j++) acc[i][j] = 0.f;

        const int rbase = warp * 4;
#pragma unroll
        for (int p = 0; p < 8; p++) {
            int k = p * 128 + lane * 4;
            float4 h0 = *(const float4*)&h_s[k];
            float4 h1 = *(const float4*)&h_s[H + k];
            float4 h2 = *(const float4*)&h_s[2 * H + k];
            float4 h3 = *(const float4*)&h_s[3 * H + k];
#pragma unroll
            for (int i = 0; i < 4; i++) {
                float4 w = *(const float4*)&whh_s[(rbase + i) * WPAD + k];
                acc[i][0] += w.x*h0.x + w.y*h0.y + w.z*h0.z + w.w*h0.w;
                acc[i][1] += w.x*h1.x + w.y*h1.y + w.z*h1.z + w.w*h1.w;
                acc[i][2] += w.x*h2.x + w.y*h2.y + w.z*h2.z + w.w*h2.w;
                acc[i][3] += w.x*h3.x + w.y*h3.y + w.z*h3.z + w.w*h3.w;
            }
        }
#pragma unroll
        for (int i = 0; i < 4; i++)
#pragma unroll
            for (int j = 0; j < 4; j++) {
                float v = acc[i][j];
                v += __shfl_xor_sync(0xffffffffu, v, 16);
                v += __shfl_xor_sync(0xffffffffu, v, 8);
                v += __shfl_xor_sync(0xffffffffu, v, 4);
                v += __shfl_xor_sync(0xffffffffu, v, 2);
                v += __shfl_xor_sync(0xffffffffu, v, 1);
                acc[i][j] = v;
            }
        if (lane == 0) {
#pragma unroll
            for (int i = 0; i < 4; i++)
#pragma unroll
                for (int j = 0; j < 4; j++)
                    z_s[(rbase + i) * 4 + j] = acc[i][j];
        }
        __syncthreads();

        // gates + state update (32 threads: uu x b)
        if (tid < 32) {
            float zi = z_s[uu * 4 + b] + p0;
            float zf = z_s[(8 + uu) * 4 + b] + p1;
            float zg = z_s[(16 + uu) * 4 + b] + p2;
            float zo = z_s[(24 + uu) * 4 + b] + p3;
            float ig = 1.f / (1.f + __expf(-zi));
            float fg = 1.f / (1.f + __expf(-zf));
            float gg = tanhf(zg);
            float og = 1.f / (1.f + __expf(-zo));
            float c = fg * c_s[tid] + ig * gg;
            c_s[tid] = c;
            float hval = og * tanhf(c);
            int col = cta * UPC + uu;
            __stcg(&g_h[(t & 1) * BSZ * H + b * H + col], hval);
            hs[((size_t)(b * TLEN + t)) * H + col] = hval;
        }
        __syncthreads();

        // ---- mailbox grid barrier ----
        const int token = t + 1;
        if (tid == 0)
            asm volatile("st.release.gpu.s32 [%0], %1;"
                         :: "l"(&g_slots[cta * 32]), "r"(token) : "memory");
        if (cta == 0) {
            if (tid < NCTA_R) {
                int v;
                do {
                    asm volatile("ld.acquire.gpu.s32 %0, [%1];"
                                 : "=r"(v) : "l"(&g_slots[tid * 32]) : "memory");
                } while (v < token);
            }
            __syncthreads();
            if (tid == 0)
                asm volatile("st.release.gpu.s32 [%0], %1;"
                             :: "l"(&g_flag), "r"(token) : "memory");
        } else {
            if (tid == 0) {
                int f;
                do {
                    asm volatile("ld.acquire.gpu.s32 %0, [%1];"
                                 : "=r"(f) : "l"(&g_flag) : "memory");
                } while (f < token);
            }
            __syncthreads();
        }
    }

    // ---- exit round: confirm everyone passed, then reset state to 0 ----
    if (tid == 0)
        asm volatile("st.release.gpu.s32 [%0], %1;"
                     :: "l"(&g_slots[cta * 32]), "r"(TLEN + 1) : "memory");
    if (cta == 0) {
        if (tid < NCTA_R) {
            int v;
            do {
                asm volatile("ld.acquire.gpu.s32 %0, [%1];"
                             : "=r"(v) : "l"(&g_slots[tid * 32]) : "memory");
            } while (v < TLEN + 1);
        }
        __syncthreads();
        if (tid < NCTA_R)
            asm volatile("st.relaxed.gpu.s32 [%0], %1;"
                         :: "l"(&g_slots[tid * 32]), "r"(0) : "memory");
        if (tid == 0)
            asm volatile("st.relaxed.gpu.s32 [%0], %1;"
                         :: "l"(&g_flag), "r"(0) : "memory");
    }
}

// ---------------------------------------------------------------------------
// Host launcher (graph-capturable: kernels only)
// ---------------------------------------------------------------------------
extern "C" void kernel_launch(void* const* d_in, const int* in_sizes, int n_in,
                              void* d_out, int out_size)
{
    (void)in_sizes; (void)n_in; (void)out_size;
    const int*   x     = (const int*)  d_in[0];
    const float* emb   = (const float*)d_in[1];
    const float* Wproj = (const float*)d_in[2];
    const float* bproj = (const float*)d_in[3];
    const float* Wih0  = (const float*)d_in[4];
    const float* Whh0  = (const float*)d_in[5];
    const float* bih0  = (const float*)d_in[6];
    const float* bhh0  = (const float*)d_in[7];
    const float* Wih1  = (const float*)d_in[8];
    const float* Whh1  = (const float*)d_in[9];
    const float* bih1  = (const float*)d_in[10];
    const float* bhh1  = (const float*)d_in[11];
    float* out = (float*)d_out;

    float *act, *pre, *hs0, *hs1;
    cudaGetSymbolAddress((void**)&act, g_act);
    cudaGetSymbolAddress((void**)&pre, g_pre);
    cudaGetSymbolAddress((void**)&hs0, g_hs0);
    cudaGetSymbolAddress((void**)&hs1, g_hs1);

    const int RSMEM = (RPC * WPAD + BSZ * H + RPC * BSZ + 32) * 4;
    cudaFuncSetAttribute(lstm_recurrent,
                         cudaFuncAttributeMaxDynamicSharedMemorySize, RSMEM);

    // 1) embedding
    embed_kernel<<<NTOK, 256>>>(x, emb, act);

    // 2) layer 0
    dim3 g1(G4H / 128, NTOK / 128);
    sgemm_abt<<<g1, 256>>>(act, Wih0, bih0, bhh0, pre, NTOK, G4H, H);
    lstm_recurrent<<<NCTA_R, TPB_R, RSMEM>>>(pre, Whh0, hs0);

    // 3) layer 1
    sgemm_abt<<<g1, 256>>>(hs0, Wih1, bih1, bhh1, pre, NTOK, G4H, H);
    lstm_recurrent<<<NCTA_R, TPB_R, RSMEM>>>(pre, Whh1, hs1);

    // 4) projection
    dim3 g2(VOCAB / 128, NTOK / 128);
    sgemm_abt<<<g2, 256>>>(hs1, Wproj, bproj, nullptr, out, NTOK, VOCAB, H);
}

// round 11
// speedup vs baseline: 1.0576x; 1.0576x over previous
#include <cuda_runtime.h>
#include <cstddef>

// Problem constants
#define H      1024
#define BSZ    4
#define TLEN   1024
#define G4H    4096          // 4*H
#define NTOK   4096          // BSZ*TLEN
#define VOCAB  32000

// Recurrent kernel config
#define NCTA_R 128
#define TPB_R  256
#define UPC    8             // hidden units per CTA (H / NCTA_R)
#define RPC    32            // gate rows per CTA (4*UPC)
#define WPAD   1028          // padded row stride for Whh slice in smem

// Pipeline config
#define NCHUNK 8
#define TCH    (TLEN / NCHUNK)   // 128 steps per chunk

// Scratch (device globals; no allocations allowed)
__device__ float g_act[(size_t)NTOK * H];
__device__ float g_pre[(size_t)NTOK * G4H];
__device__ float g_hs0[(size_t)NTOK * H];
__device__ float g_hs1[(size_t)NTOK * H];
__device__ float g_hc0[BSZ * H];     // layer-0 h carry
__device__ float g_hc1[BSZ * H];     // layer-1 h carry
__device__ float g_cc0[BSZ * H];     // layer-0 c carry
__device__ float g_cc1[BSZ * H];     // layer-1 c carry
__device__ int g_bar_count;          // returns to 0 every launch
__device__ int g_bar_flag;           // even # of toggles per launch -> returns to 0

// ---------------------------------------------------------------------------
// Packed fp32x2 helpers (FFMA2)
// ---------------------------------------------------------------------------
__device__ __forceinline__ unsigned long long pk2(float x, float y) {
    unsigned long long r;
    asm("mov.b64 %0, {%1, %2};" : "=l"(r) : "f"(x), "f"(y));
    return r;
}
__device__ __forceinline__ void ffma2(unsigned long long& d,
                                      unsigned long long a,
                                      unsigned long long b) {
    asm("fma.rn.f32x2 %0, %1, %2, %0;" : "+l"(d) : "l"(a), "l"(b));
}
__device__ __forceinline__ float2 upk2(unsigned long long v) {
    float2 f;
    asm("mov.b64 {%0, %1}, %2;" : "=f"(f.x), "=f"(f.y) : "l"(v));
    return f;
}

// ---------------------------------------------------------------------------
// Embedding gather: out[n, :] = emb[x[n], :]
// ---------------------------------------------------------------------------
__global__ void embed_kernel(const int* __restrict__ x,
                             const float* __restrict__ emb,
                             float* __restrict__ out)
{
    int n = blockIdx.x;
    int tok = __ldg(&x[n]);
    const float4* src = (const float4*)(emb + (size_t)tok * H);
    float4* dst = (float4*)(out + (size_t)n * H);
    dst[threadIdx.x] = __ldg(&src[threadIdx.x]);
}

// ---------------------------------------------------------------------------
// Chunked SGEMM over a T-slice: rows m = b*TLEN + t0 + [0,TCH) for each b.
// C[m, :N] = A[m, :K] * B[N,K]^T + bias1 (+bias2).  grid = (N/128, BSZ).
// Inner kernel identical to R6 (128x128x16 tiles, FFMA2).
// ---------------------------------------------------------------------------
__global__ __launch_bounds__(256, 2)
void sgemm_abt(const float* __restrict__ A, const float* __restrict__ B,
               const float* __restrict__ bias1, const float* __restrict__ bias2,
               float* __restrict__ C, int N, int K, int t0)
{
    __shared__ float As[16][132];
    __shared__ float Bs[16][132];
    const int tid = threadIdx.x;
    const int bm = blockIdx.y * TLEN + t0;
    const int bn = blockIdx.x * 128;
    const int tx = tid & 15;
    const int ty = tid >> 4;
    const int lr = tid >> 2;          // 0..63
    const int lk = (tid & 3) << 2;    // 0,4,8,12

    const float* Ag = A + (size_t)(bm + lr) * K + lk;
    const float* Bg = B + (size_t)(bn + lr) * K + lk;

    unsigned long long acc2[4][8];
#pragma unroll
    for (int i = 0; i < 4; i++)
#pragma unroll
        for (int j = 0; j < 8; j++) acc2[i][j] = 0ull;

    float4 a0 = *(const float4*)(Ag);
    float4 a1 = *(const float4*)(Ag + (size_t)64 * K);
    float4 b0 = *(const float4*)(Bg);
    float4 b1 = *(const float4*)(Bg + (size_t)64 * K);

    for (int k0 = 0; k0 < K; k0 += 16) {
        __syncthreads();
        As[lk+0][lr]    = a0.x; As[lk+1][lr]    = a0.y; As[lk+2][lr]    = a0.z; As[lk+3][lr]    = a0.w;
        As[lk+0][lr+64] = a1.x; As[lk+1][lr+64] = a1.y; As[lk+2][lr+64] = a1.z; As[lk+3][lr+64] = a1.w;
        Bs[lk+0][lr]    = b0.x; Bs[lk+1][lr]    = b0.y; Bs[lk+2][lr]    = b0.z; Bs[lk+3][lr]    = b0.w;
        Bs[lk+0][lr+64] = b1.x; Bs[lk+1][lr+64] = b1.y; Bs[lk+2][lr+64] = b1.z; Bs[lk+3][lr+64] = b1.w;
        __syncthreads();
        if (k0 + 16 < K) {
            a0 = *(const float4*)(Ag + k0 + 16);
            a1 = *(const float4*)(Ag + (size_t)64 * K + k0 + 16);
            b0 = *(const float4*)(Bg + k0 + 16);
            b1 = *(const float4*)(Bg + (size_t)64 * K + k0 + 16);
        }
#pragma unroll
        for (int k = 0; k < 16; k++) {
            float4 aA = *(const float4*)&As[k][ty * 4];
            float4 aB = *(const float4*)&As[k][64 + ty * 4];
            float4 bA = *(const float4*)&Bs[k][tx * 4];
            float4 bB = *(const float4*)&Bs[k][64 + tx * 4];
            unsigned long long av2[4];
            av2[0] = pk2(aA.x, aA.y);
            av2[1] = pk2(aA.z, aA.w);
            av2[2] = pk2(aB.x, aB.y);
            av2[3] = pk2(aB.z, aB.w);
            unsigned long long bv2[8];
            bv2[0] = pk2(bA.x, bA.x);
            bv2[1] = pk2(bA.y, bA.y);
            bv2[2] = pk2(bA.z, bA.z);
            bv2[3] = pk2(bA.w, bA.w);
            bv2[4] = pk2(bB.x, bB.x);
            bv2[5] = pk2(bB.y, bB.y);
            bv2[6] = pk2(bB.z, bB.z);
            bv2[7] = pk2(bB.w, bB.w);
#pragma unroll
            for (int i = 0; i < 4; i++)
#pragma unroll
                for (int j = 0; j < 8; j++)
                    ffma2(acc2[i][j], av2[i], bv2[j]);
        }
    }

    float acc[8][8];
#pragma unroll
    for (int i2 = 0; i2 < 4; i2++)
#pragma unroll
        for (int j = 0; j < 8; j++) {
            float2 v = upk2(acc2[i2][j]);
            acc[2 * i2][j]     = v.x;
            acc[2 * i2 + 1][j] = v.y;
        }

    float bb[8];
#pragma unroll
    for (int jh = 0; jh < 2; jh++)
#pragma unroll
        for (int j = 0; j < 4; j++) {
            int n = bn + jh * 64 + tx * 4 + j;
            float v = bias1 ? __ldg(&bias1[n]) : 0.f;
            if (bias2) v += __ldg(&bias2[n]);
            bb[jh * 4 + j] = v;
        }
#pragma unroll
    for (int ih = 0; ih < 2; ih++)
#pragma unroll
        for (int i = 0; i < 4; i++) {
            int m = bm + ih * 64 + ty * 4 + i;
#pragma unroll
            for (int jh = 0; jh < 2; jh++) {
                float4 v;
                v.x = acc[ih*4+i][jh*4+0] + bb[jh*4+0];
                v.y = acc[ih*4+i][jh*4+1] + bb[jh*4+1];
                v.z = acc[ih*4+i][jh*4+2] + bb[jh*4+2];
                v.w = acc[ih*4+i][jh*4+3] + bb[jh*4+3];
                *(float4*)&C[(size_t)m * N + bn + jh * 64 + tx * 4] = v;
            }
        }
}

// ---------------------------------------------------------------------------
// Persistent LSTM recurrence, chunked: steps [t0, t0+TCH). R6-exact step body
// and flat-atomic grid barrier. Per-layer h/c carries in device globals so
// layer-0 and layer-1 chunk launches can interleave on one stream.
// ---------------------------------------------------------------------------
__global__ __launch_bounds__(TPB_R)
void lstm_recurrent(const float* __restrict__ pre,
                    const float* __restrict__ Whh,
                    float* __restrict__ hs,
                    float* __restrict__ hcarry,
                    float* __restrict__ ccarry,
                    int t0)
{
    extern __shared__ float sm[];
    float* whh_s = sm;                       // RPC * WPAD
    float* h_s   = sm + RPC * WPAD;          // BSZ * H
    float* z_s   = h_s + BSZ * H;            // RPC * BSZ
    float* c_s   = z_s + RPC * BSZ;          // 32

    const int tid  = threadIdx.x;
    const int cta  = blockIdx.x;
    const int warp = tid >> 5;
    const int lane = tid & 31;

    for (int i = tid; i < RPC * H; i += TPB_R) {
        int r = i >> 10;
        int k = i & (H - 1);
        int q = r >> 3;
        int uu = r & 7;
        int grow = q * H + cta * UPC + uu;
        whh_s[r * WPAD + k] = __ldg(&Whh[(size_t)grow * H + k]);
    }
    if (tid < 32) {
        int uu_ = tid >> 2, b_ = tid & 3;
        int col_ = cta * UPC + uu_;
        c_s[tid] = (t0 == 0) ? 0.f : __ldcg(&ccarry[b_ * H + col_]);
    }
    int sense = 0;
    __syncthreads();

    for (int t = t0; t < t0 + TCH; t++) {
        // h(t-1) into smem (zeros at t=0)
        float4* hs4 = (float4*)h_s;
        if (t == 0) {
            for (int i = tid; i < (BSZ * H) / 4; i += TPB_R)
                hs4[i] = make_float4(0.f, 0.f, 0.f, 0.f);
        } else {
            const float4* hg = (const float4*)hcarry;
            for (int i = tid; i < (BSZ * H) / 4; i += TPB_R)
                hs4[i] = __ldcg(hg + i);
        }
        // prefetch pre-activations for gate threads
        float p0 = 0.f, p1 = 0.f, p2 = 0.f, p3 = 0.f;
        int uu = 0, b = 0;
        if (tid < 32) {
            uu = tid >> 2; b = tid & 3;
            size_t base = ((size_t)(b * TLEN + t)) * G4H + cta * UPC + uu;
            p0 = __ldg(&pre[base]);
            p1 = __ldg(&pre[base + H]);
            p2 = __ldg(&pre[base + 2 * H]);
            p3 = __ldg(&pre[base + 3 * H]);
        }
        __syncthreads();

        // z[r][b] = sum_k Whh_s[r][k] * h[b][k]; warp owns 4 rows, all 4 b.
        float acc[4][4];
#pragma unroll
        for (int i = 0; i < 4; i++)
#pragma unroll
            for (int j = 0; j < 4; j++) acc[i][j] = 0.f;

        const int rbase = warp * 4;
#pragma unroll
        for (int p = 0; p < 8; p++) {
            int k = p * 128 + lane * 4;
            float4 h0 = *(const float4*)&h_s[k];
            float4 h1 = *(const float4*)&h_s[H + k];
            float4 h2 = *(const float4*)&h_s[2 * H + k];
            float4 h3 = *(const float4*)&h_s[3 * H + k];
#pragma unroll
            for (int i = 0; i < 4; i++) {
                float4 w = *(const float4*)&whh_s[(rbase + i) * WPAD + k];
                acc[i][0] += w.x*h0.x + w.y*h0.y + w.z*h0.z + w.w*h0.w;
                acc[i][1] += w.x*h1.x + w.y*h1.y + w.z*h1.z + w.w*h1.w;
                acc[i][2] += w.x*h2.x + w.y*h2.y + w.z*h2.z + w.w*h2.w;
                acc[i][3] += w.x*h3.x + w.y*h3.y + w.z*h3.z + w.w*h3.w;
            }
        }
#pragma unroll
        for (int i = 0; i < 4; i++)
#pragma unroll
            for (int j = 0; j < 4; j++) {
                float v = acc[i][j];
                v += __shfl_xor_sync(0xffffffffu, v, 16);
                v += __shfl_xor_sync(0xffffffffu, v, 8);
                v += __shfl_xor_sync(0xffffffffu, v, 4);
                v += __shfl_xor_sync(0xffffffffu, v, 2);
                v += __shfl_xor_sync(0xffffffffu, v, 1);
                acc[i][j] = v;
            }
        if (lane == 0) {
#pragma unroll
            for (int i = 0; i < 4; i++)
#pragma unroll
                for (int j = 0; j < 4; j++)
                    z_s[(rbase + i) * 4 + j] = acc[i][j];
        }
        __syncthreads();

        // gates + state update (32 threads: uu x b)
        if (tid < 32) {
            float zi = z_s[uu * 4 + b] + p0;
            float zf = z_s[(8 + uu) * 4 + b] + p1;
            float zg = z_s[(16 + uu) * 4 + b] + p2;
            float zo = z_s[(24 + uu) * 4 + b] + p3;
            float ig = 1.f / (1.f + __expf(-zi));
            float fg = 1.f / (1.f + __expf(-zf));
            float gg = tanhf(zg);
            float og = 1.f / (1.f + __expf(-zo));
            float c = fg * c_s[tid] + ig * gg;
            c_s[tid] = c;
            float hval = og * tanhf(c);
            int col = cta * UPC + uu;
            __stcg(&hcarry[b * H + col], hval);
            hs[((size_t)(b * TLEN + t)) * H + col] = hval;
        }
        __syncthreads();

        // flat grid barrier (R6-exact)
        if (tid == 0) {
            sense ^= 1;
            int prev;
            asm volatile("atom.add.acq_rel.gpu.s32 %0, [%1], 1;"
                         : "=r"(prev) : "l"(&g_bar_count) : "memory");
            if (prev == NCTA_R - 1) {
                asm volatile("st.relaxed.gpu.s32 [%0], %1;"
                             :: "l"(&g_bar_count), "r"(0) : "memory");
                asm volatile("st.release.gpu.s32 [%0], %1;"
                             :: "l"(&g_bar_flag), "r"(sense) : "memory");
            } else {
                int f;
                do {
                    asm volatile("ld.acquire.gpu.s32 %0, [%1];"
                                 : "=r"(f) : "l"(&g_bar_flag) : "memory");
                } while (f != sense);
            }
        }
        __syncthreads();
    }

    // save c-state for next chunk
    if (tid < 32) {
        int uu_ = tid >> 2, b_ = tid & 3;
        int col_ = cta * UPC + uu_;
        __stcg(&ccarry[b_ * H + col_], c_s[tid]);
    }
}

// ---------------------------------------------------------------------------
// Host launcher: 3-stream chunked pipeline, graph-capturable (fork/join events)
// ---------------------------------------------------------------------------
extern "C" void kernel_launch(void* const* d_in, const int* in_sizes, int n_in,
                              void* d_out, int out_size)
{
    (void)in_sizes; (void)n_in; (void)out_size;
    const int*   x     = (const int*)  d_in[0];
    const float* emb   = (const float*)d_in[1];
    const float* Wproj = (const float*)d_in[2];
    const float* bproj = (const float*)d_in[3];
    const float* Wih0  = (const float*)d_in[4];
    const float* Whh0  = (const float*)d_in[5];
    const float* bih0  = (const float*)d_in[6];
    const float* bhh0  = (const float*)d_in[7];
    const float* Wih1  = (const float*)d_in[8];
    const float* Whh1  = (const float*)d_in[9];
    const float* bih1  = (const float*)d_in[10];
    const float* bhh1  = (const float*)d_in[11];
    float* out = (float*)d_out;

    static int inited = 0;
    static cudaStream_t s1, s2;
    static cudaEvent_t evEmbed, evJoin;
    static cudaEvent_t evPre0[NCHUNK], evRec0[NCHUNK], evPre1[NCHUNK], evRec1[NCHUNK];
    if (!inited) {
        cudaStreamCreateWithFlags(&s1, cudaStreamNonBlocking);
        cudaStreamCreateWithFlags(&s2, cudaStreamNonBlocking);
        cudaEventCreateWithFlags(&evEmbed, cudaEventDisableTiming);
        cudaEventCreateWithFlags(&evJoin, cudaEventDisableTiming);
        for (int c = 0; c < NCHUNK; c++) {
            cudaEventCreateWithFlags(&evPre0[c], cudaEventDisableTiming);
            cudaEventCreateWithFlags(&evRec0[c], cudaEventDisableTiming);
            cudaEventCreateWithFlags(&evPre1[c], cudaEventDisableTiming);
            cudaEventCreateWithFlags(&evRec1[c], cudaEventDisableTiming);
        }
        inited = 1;
    }

    float *act, *pre, *hs0, *hs1, *hc0, *hc1, *cc0, *cc1;
    cudaGetSymbolAddress((void**)&act, g_act);
    cudaGetSymbolAddress((void**)&pre, g_pre);
    cudaGetSymbolAddress((void**)&hs0, g_hs0);
    cudaGetSymbolAddress((void**)&hs1, g_hs1);
    cudaGetSymbolAddress((void**)&hc0, g_hc0);
    cudaGetSymbolAddress((void**)&hc1, g_hc1);
    cudaGetSymbolAddress((void**)&cc0, g_cc0);
    cudaGetSymbolAddress((void**)&cc1, g_cc1);

    const int RSMEM = (RPC * WPAD + BSZ * H + RPC * BSZ + 32) * 4;
    cudaFuncSetAttribute(lstm_recurrent,
                         cudaFuncAttributeMaxDynamicSharedMemorySize, RSMEM);

    const dim3 gPre(G4H / 128, BSZ);       // 32 x 4 CTAs per chunk
    const dim3 gProj(VOCAB / 128, BSZ);    // 250 x 4 CTAs per chunk

    // --- embedding on s0 (captured origin stream) ---
    embed_kernel<<<NTOK, 256>>>(x, emb, act);
    cudaEventRecord(evEmbed, 0);

    // --- pre0 chunk 0 on s0 (rec0(0) follows in-stream) ---
    sgemm_abt<<<gPre, 256>>>(act, Wih0, bih0, bhh0, pre, G4H, H, 0);

    // --- pre0 chunks 1..7 on s1 (overlap rec0(0)) ---
    cudaStreamWaitEvent(s1, evEmbed, 0);
    for (int c = 1; c < NCHUNK; c++) {
        sgemm_abt<<<gPre, 256, 0, s1>>>(act, Wih0, bih0, bhh0, pre, G4H, H, c * TCH);
        cudaEventRecord(evPre0[c], s1);
    }

    // --- rec0(0) + pre1(0) ---
    lstm_recurrent<<<NCTA_R, TPB_R, RSMEM>>>(pre, Whh0, hs0, hc0, cc0, 0);
    cudaEventRecord(evRec0[0], 0);
    cudaStreamWaitEvent(s1, evRec0[0], 0);
    sgemm_abt<<<gPre, 256, 0, s1>>>(hs0, Wih1, bih1, bhh1, pre, G4H, H, 0);
    cudaEventRecord(evPre1[0], s1);

    // --- pipeline: rec0(c) | pre1(c) | rec1(c-1) | proj(c-1) ---
    for (int c = 1; c < NCHUNK; c++) {
        cudaStreamWaitEvent(0, evPre0[c], 0);
        lstm_recurrent<<<NCTA_R, TPB_R, RSMEM>>>(pre, Whh0, hs0, hc0, cc0, c * TCH);
        cudaEventRecord(evRec0[c], 0);

        cudaStreamWaitEvent(s1, evRec0[c], 0);
        sgemm_abt<<<gPre, 256, 0, s1>>>(hs0, Wih1, bih1, bhh1, pre, G4H, H, c * TCH);
        cudaEventRecord(evPre1[c], s1);

        cudaStreamWaitEvent(0, evPre1[c - 1], 0);
        lstm_recurrent<<<NCTA_R, TPB_R, RSMEM>>>(pre, Whh1, hs1, hc1, cc1, (c - 1) * TCH);
        cudaEventRecord(evRec1[c - 1], 0);

        cudaStreamWaitEvent(s2, evRec1[c - 1], 0);
        sgemm_abt<<<gProj, 256, 0, s2>>>(hs1, Wproj, bproj, nullptr, out,
                                         VOCAB, H, (c - 1) * TCH);
    }

    // --- tail: rec1(7) + proj(7), then join s2 back into s0 ---
    cudaStreamWaitEvent(0, evPre1[NCHUNK - 1], 0);
    lstm_recurrent<<<NCTA_R, TPB_R, RSMEM>>>(pre, Whh1, hs1, hc1, cc1,
                                             (NCHUNK - 1) * TCH);
    cudaEventRecord(evRec1[NCHUNK - 1], 0);
    cudaStreamWaitEvent(s2, evRec1[NCHUNK - 1], 0);
    sgemm_abt<<<gProj, 256, 0, s2>>>(hs1, Wproj, bproj, nullptr, out,
                                     VOCAB, H, (NCHUNK - 1) * TCH);
    cudaEventRecord(evJoin, s2);
    cudaStreamWaitEvent(0, evJoin, 0);
}

// round 12
// speedup vs baseline: 1.2126x; 1.1466x over previous
#include <cuda_runtime.h>
#include <cstddef>

// Problem constants
#define H      1024
#define BSZ    4
#define TLEN   1024
#define G4H    4096          // 4*H
#define NTOK   4096          // BSZ*TLEN
#define VOCAB  32000

// Fused recurrent kernel config
#define NCTA_R 128
#define TPB_R  256
#define UPC    8             // hidden units per CTA per layer
#define RPC    32            // gate rows per CTA per layer (4*UPC)
#define WPAD   1028          // padded row stride for Whh0 slice in smem

// Scratch (device globals; no allocations allowed)
__device__ float g_act[(size_t)NTOK * H];
__device__ float g_pre[(size_t)NTOK * G4H];
__device__ float g_hs1[(size_t)NTOK * H];
__device__ float g_h0[2 * BSZ * H];      // layer-0 h carry, parity buffered
__device__ float g_h1[2 * BSZ * H];      // layer-1 h carry, parity buffered
__device__ int g_bar_count;              // returns to 0 every launch
__device__ int g_bar_flag;               // even # of toggles per launch -> 0

// ---------------------------------------------------------------------------
// Packed fp32x2 helpers (FFMA2) for the SGEMM
// ---------------------------------------------------------------------------
__device__ __forceinline__ unsigned long long pk2(float x, float y) {
    unsigned long long r;
    asm("mov.b64 %0, {%1, %2};" : "=l"(r) : "f"(x), "f"(y));
    return r;
}
__device__ __forceinline__ void ffma2(unsigned long long& d,
                                      unsigned long long a,
                                      unsigned long long b) {
    asm("fma.rn.f32x2 %0, %1, %2, %0;" : "+l"(d) : "l"(a), "l"(b));
}
__device__ __forceinline__ float2 upk2(unsigned long long v) {
    float2 f;
    asm("mov.b64 {%0, %1}, %2;" : "=f"(f.x), "=f"(f.y) : "l"(v));
    return f;
}

// flat grid barrier, R6-exact (acq_rel arrival, release publish, acquire poll)
__device__ __forceinline__ void grid_barrier(int tid, int& sense) {
    if (tid == 0) {
        sense ^= 1;
        int prev;
        asm volatile("atom.add.acq_rel.gpu.s32 %0, [%1], 1;"
                     : "=r"(prev) : "l"(&g_bar_count) : "memory");
        if (prev == NCTA_R - 1) {
            asm volatile("st.relaxed.gpu.s32 [%0], %1;"
                         :: "l"(&g_bar_count), "r"(0) : "memory");
            asm volatile("st.release.gpu.s32 [%0], %1;"
                         :: "l"(&g_bar_flag), "r"(sense) : "memory");
        } else {
            int f;
            do {
                asm volatile("ld.acquire.gpu.s32 %0, [%1];"
                             : "=r"(f) : "l"(&g_bar_flag) : "memory");
            } while (f != sense);
        }
    }
    __syncthreads();
}

// ---------------------------------------------------------------------------
// Embedding gather: out[n, :] = emb[x[n], :]
// ---------------------------------------------------------------------------
__global__ void embed_kernel(const int* __restrict__ x,
                             const float* __restrict__ emb,
                             float* __restrict__ out)
{
    int n = blockIdx.x;
    int tok = __ldg(&x[n]);
    const float4* src = (const float4*)(emb + (size_t)tok * H);
    float4* dst = (float4*)(out + (size_t)n * H);
    dst[threadIdx.x] = __ldg(&src[threadIdx.x]);
}

// ---------------------------------------------------------------------------
// SGEMM: C[M,N] = A[M,K] * B[N,K]^T + bias1[N] (+ bias2[N])   (R6-exact)
// ---------------------------------------------------------------------------
__global__ __launch_bounds__(256, 2)
void sgemm_abt(const float* __restrict__ A, const float* __restrict__ B,
               const float* __restrict__ bias1, const float* __restrict__ bias2,
               float* __restrict__ C, int M, int N, int K)
{
    __shared__ float As[16][132];
    __shared__ float Bs[16][132];
    const int tid = threadIdx.x;
    const int bm = blockIdx.y * 128;
    const int bn = blockIdx.x * 128;
    const int tx = tid & 15;
    const int ty = tid >> 4;
    const int lr = tid >> 2;          // 0..63
    const int lk = (tid & 3) << 2;    // 0,4,8,12

    const float* Ag = A + (size_t)(bm + lr) * K + lk;
    const float* Bg = B + (size_t)(bn + lr) * K + lk;

    unsigned long long acc2[4][8];
#pragma unroll
    for (int i = 0; i < 4; i++)
#pragma unroll
        for (int j = 0; j < 8; j++) acc2[i][j] = 0ull;

    float4 a0 = *(const float4*)(Ag);
    float4 a1 = *(const float4*)(Ag + (size_t)64 * K);
    float4 b0 = *(const float4*)(Bg);
    float4 b1 = *(const float4*)(Bg + (size_t)64 * K);

    for (int k0 = 0; k0 < K; k0 += 16) {
        __syncthreads();
        As[lk+0][lr]    = a0.x; As[lk+1][lr]    = a0.y; As[lk+2][lr]    = a0.z; As[lk+3][lr]    = a0.w;
        As[lk+0][lr+64] = a1.x; As[lk+1][lr+64] = a1.y; As[lk+2][lr+64] = a1.z; As[lk+3][lr+64] = a1.w;
        Bs[lk+0][lr]    = b0.x; Bs[lk+1][lr]    = b0.y; Bs[lk+2][lr]    = b0.z; Bs[lk+3][lr]    = b0.w;
        Bs[lk+0][lr+64] = b1.x; Bs[lk+1][lr+64] = b1.y; Bs[lk+2][lr+64] = b1.z; Bs[lk+3][lr+64] = b1.w;
        __syncthreads();
        if (k0 + 16 < K) {
            a0 = *(const float4*)(Ag + k0 + 16);
            a1 = *(const float4*)(Ag + (size_t)64 * K + k0 + 16);
            b0 = *(const float4*)(Bg + k0 + 16);
            b1 = *(const float4*)(Bg + (size_t)64 * K + k0 + 16);
        }
#pragma unroll
        for (int k = 0; k < 16; k++) {
            float4 aA = *(const float4*)&As[k][ty * 4];
            float4 aB = *(const float4*)&As[k][64 + ty * 4];
            float4 bA = *(const float4*)&Bs[k][tx * 4];
            float4 bB = *(const float4*)&Bs[k][64 + tx * 4];
            unsigned long long av2[4];
            av2[0] = pk2(aA.x, aA.y);
            av2[1] = pk2(aA.z, aA.w);
            av2[2] = pk2(aB.x, aB.y);
            av2[3] = pk2(aB.z, aB.w);
            unsigned long long bv2[8];
            bv2[0] = pk2(bA.x, bA.x);
            bv2[1] = pk2(bA.y, bA.y);
            bv2[2] = pk2(bA.z, bA.z);
            bv2[3] = pk2(bA.w, bA.w);
            bv2[4] = pk2(bB.x, bB.x);
            bv2[5] = pk2(bB.y, bB.y);
            bv2[6] = pk2(bB.z, bB.z);
            bv2[7] = pk2(bB.w, bB.w);
#pragma unroll
            for (int i = 0; i < 4; i++)
#pragma unroll
                for (int j = 0; j < 8; j++)
                    ffma2(acc2[i][j], av2[i], bv2[j]);
        }
    }

    float acc[8][8];
#pragma unroll
    for (int i2 = 0; i2 < 4; i2++)
#pragma unroll
        for (int j = 0; j < 8; j++) {
            float2 v = upk2(acc2[i2][j]);
            acc[2 * i2][j]     = v.x;
            acc[2 * i2 + 1][j] = v.y;
        }

    float bb[8];
#pragma unroll
    for (int jh = 0; jh < 2; jh++)
#pragma unroll
        for (int j = 0; j < 4; j++) {
            int n = bn + jh * 64 + tx * 4 + j;
            float v = bias1 ? __ldg(&bias1[n]) : 0.f;
            if (bias2) v += __ldg(&bias2[n]);
            bb[jh * 4 + j] = v;
        }
#pragma unroll
    for (int ih = 0; ih < 2; ih++)
#pragma unroll
        for (int i = 0; i < 4; i++) {
            int m = bm + ih * 64 + ty * 4 + i;
#pragma unroll
            for (int jh = 0; jh < 2; jh++) {
                float4 v;
                v.x = acc[ih*4+i][jh*4+0] + bb[jh*4+0];
                v.y = acc[ih*4+i][jh*4+1] + bb[jh*4+1];
                v.z = acc[ih*4+i][jh*4+2] + bb[jh*4+2];
                v.w = acc[ih*4+i][jh*4+3] + bb[jh*4+3];
                *(float4*)&C[(size_t)m * N + bn + jh * 64 + tx * 4] = v;
            }
        }
}

// ---------------------------------------------------------------------------
// Fused two-layer wavefront LSTM. 128 resident CTAs; CTA owns 8 hidden units
// of BOTH layers. Superstep s: layer-0 step t=s (Whh0 SMEM-resident) AND
// layer-1 step t=s-1 (Whh1 + Wih1 streamed from L2 via __ldcg — this also
// subsumes the pre1 GEMM). One grid barrier per superstep (1026 total, even).
// h carries parity-double-buffered: publish to [s&1], read from [(s-1)&1];
// a CTA cannot enter superstep s+1 until all CTAs passed barrier s, so
// reads at s strictly precede writes at s+1. Race-free.
// ---------------------------------------------------------------------------
__global__ __launch_bounds__(TPB_R, 1)
void lstm_fused(const float* __restrict__ pre0,
                const float* __restrict__ Whh0,
                const float* __restrict__ Whh1,
                const float* __restrict__ Wih1,
                const float* __restrict__ bih1,
                const float* __restrict__ bhh1,
                float* __restrict__ hs1)
{
    extern __shared__ float sm[];
    float* whh0_s = sm;                        // RPC * WPAD
    float* h0_s   = whh0_s + RPC * WPAD;       // BSZ * H
    float* h1_s   = h0_s + BSZ * H;            // BSZ * H
    float* z_s    = h1_s + BSZ * H;            // 256 (layer0: 0..127, layer1: 128..255)
    float* c_s    = z_s + 256;                 // 64  (layer0: 0..31,  layer1: 32..63)

    const int tid  = threadIdx.x;
    const int cta  = blockIdx.x;
    const int warp = tid >> 5;
    const int lane = tid & 31;

    // Whh0 slice into smem: local row r = q*8+uu -> global row q*H + cta*8 + uu
    for (int i = tid; i < RPC * H; i += TPB_R) {
        int r = i >> 10;
        int k = i & (H - 1);
        int grow = (r >> 3) * H + cta * UPC + (r & 7);
        whh0_s[r * WPAD + k] = __ldg(&Whh0[(size_t)grow * H + k]);
    }
    if (tid < 64) c_s[tid] = 0.f;

    // layer-1 gate biases (constant): thread tid in [32,64) handles (u1, b1)
    float gb0 = 0.f, gb1 = 0.f, gb2 = 0.f, gb3 = 0.f;
    int u1 = 0, b1 = 0, col1 = 0;
    if (tid >= 32 && tid < 64) {
        u1 = (tid - 32) >> 2;
        b1 = (tid - 32) & 3;
        col1 = cta * UPC + u1;
        gb0 = __ldg(&bih1[col1])         + __ldg(&bhh1[col1]);
        gb1 = __ldg(&bih1[H + col1])     + __ldg(&bhh1[H + col1]);
        gb2 = __ldg(&bih1[2 * H + col1]) + __ldg(&bhh1[2 * H + col1]);
        gb3 = __ldg(&bih1[3 * H + col1]) + __ldg(&bhh1[3 * H + col1]);
    }
    // layer-0 gate mapping: tid in [0,32)
    int u0 = 0, b0 = 0, col0 = 0;
    if (tid < 32) {
        u0 = tid >> 2;
        b0 = tid & 3;
        col0 = cta * UPC + u0;
    }

    // layer-1 streamed weight row pointers for this warp's 4 rows
    const int rbase = warp * 4;
    const float* wh1p[4];
    const float* wi1p[4];
#pragma unroll
    for (int i = 0; i < 4; i++) {
        int r = rbase + i;
        size_t grow = (size_t)((r >> 3) * H + cta * UPC + (r & 7));
        wh1p[i] = Whh1 + grow * H;
        wi1p[i] = Wih1 + grow * H;
    }

    int sense = 0;
    __syncthreads();

    for (int s = 0; s <= TLEN; s++) {
        // stage h0(s-1) and h1(s-2) into smem from parity buffer (s-1)&1
        {
            float4* d0 = (float4*)h0_s;
            float4* d1 = (float4*)h1_s;
            if (s == 0) {
                for (int i = tid; i < (BSZ * H) / 4; i += TPB_R) {
                    d0[i] = make_float4(0.f, 0.f, 0.f, 0.f);
                    d1[i] = make_float4(0.f, 0.f, 0.f, 0.f);
                }
            } else {
                const float4* s0 = (const float4*)(g_h0 + ((s - 1) & 1) * BSZ * H);
                for (int i = tid; i < (BSZ * H) / 4; i += TPB_R)
                    d0[i] = __ldcg(s0 + i);
                if (s == 1) {
                    for (int i = tid; i < (BSZ * H) / 4; i += TPB_R)
                        d1[i] = make_float4(0.f, 0.f, 0.f, 0.f);
                } else {
                    const float4* s1 = (const float4*)(g_h1 + ((s - 1) & 1) * BSZ * H);
                    for (int i = tid; i < (BSZ * H) / 4; i += TPB_R)
                        d1[i] = __ldcg(s1 + i);
                }
            }
        }
        // prefetch layer-0 pre-activations (t = s), gate threads only
        float p0 = 0.f, p1 = 0.f, p2 = 0.f, p3 = 0.f;
        if (tid < 32 && s < TLEN) {
            size_t base = ((size_t)(b0 * TLEN + s)) * G4H + cta * UPC + u0;
            p0 = __ldg(&pre0[base]);
            p1 = __ldg(&pre0[base + H]);
            p2 = __ldg(&pre0[base + 2 * H]);
            p3 = __ldg(&pre0[base + 3 * H]);
        }
        __syncthreads();

        // dots: a0 = Whh0_s . h0s ; a1 = Whh1 . h1s + Wih1 . h0s (streamed)
        float a0[4][4], a1[4][4];
#pragma unroll
        for (int i = 0; i < 4; i++)
#pragma unroll
            for (int j = 0; j < 4; j++) { a0[i][j] = 0.f; a1[i][j] = 0.f; }

#pragma unroll
        for (int p = 0; p < 8; p++) {
            int k = p * 128 + lane * 4;
            float4 x0 = *(const float4*)&h0_s[k];
            float4 x1 = *(const float4*)&h0_s[H + k];
            float4 x2 = *(const float4*)&h0_s[2 * H + k];
            float4 x3 = *(const float4*)&h0_s[3 * H + k];
            float4 y0 = *(const float4*)&h1_s[k];
            float4 y1 = *(const float4*)&h1_s[H + k];
            float4 y2 = *(const float4*)&h1_s[2 * H + k];
            float4 y3 = *(const float4*)&h1_s[3 * H + k];
#pragma unroll
            for (int i = 0; i < 4; i++) {
                float4 w0 = *(const float4*)&whh0_s[(rbase + i) * WPAD + k];
                a0[i][0] += w0.x*x0.x + w0.y*x0.y + w0.z*x0.z + w0.w*x0.w;
                a0[i][1] += w0.x*x1.x + w0.y*x1.y + w0.z*x1.z + w0.w*x1.w;
                a0[i][2] += w0.x*x2.x + w0.y*x2.y + w0.z*x2.z + w0.w*x2.w;
                a0[i][3] += w0.x*x3.x + w0.y*x3.y + w0.z*x3.z + w0.w*x3.w;
                float4 wa = __ldcg((const float4*)(wh1p[i] + k));
                float4 wb = __ldcg((const float4*)(wi1p[i] + k));
                a1[i][0] += wa.x*y0.x + wa.y*y0.y + wa.z*y0.z + wa.w*y0.w
                          + wb.x*x0.x + wb.y*x0.y + wb.z*x0.z + wb.w*x0.w;
                a1[i][1] += wa.x*y1.x + wa.y*y1.y + wa.z*y1.z + wa.w*y1.w
                          + wb.x*x1.x + wb.y*x1.y + wb.z*x1.z + wb.w*x1.w;
                a1[i][2] += wa.x*y2.x + wa.y*y2.y + wa.z*y2.z + wa.w*y2.w
                          + wb.x*x2.x + wb.y*x2.y + wb.z*x2.z + wb.w*x2.w;
                a1[i][3] += wa.x*y3.x + wa.y*y3.y + wa.z*y3.z + wa.w*y3.w
                          + wb.x*x3.x + wb.y*x3.y + wb.z*x3.z + wb.w*x3.w;
            }
        }
        // warp reductions (32 chains)
#pragma unroll
        for (int i = 0; i < 4; i++)
#pragma unroll
            for (int j = 0; j < 4; j++) {
                float v = a0[i][j];
                v += __shfl_xor_sync(0xffffffffu, v, 16);
                v += __shfl_xor_sync(0xffffffffu, v, 8);
                v += __shfl_xor_sync(0xffffffffu, v, 4);
                v += __shfl_xor_sync(0xffffffffu, v, 2);
                v += __shfl_xor_sync(0xffffffffu, v, 1);
                a0[i][j] = v;
                float w = a1[i][j];
                w += __shfl_xor_sync(0xffffffffu, w, 16);
                w += __shfl_xor_sync(0xffffffffu, w, 8);
                w += __shfl_xor_sync(0xffffffffu, w, 4);
                w += __shfl_xor_sync(0xffffffffu, w, 2);
                w += __shfl_xor_sync(0xffffffffu, w, 1);
                a1[i][j] = w;
            }
        if (lane == 0) {
#pragma unroll
            for (int i = 0; i < 4; i++)
#pragma unroll
                for (int j = 0; j < 4; j++) {
                    z_s[(rbase + i) * 4 + j]       = a0[i][j];
                    z_s[128 + (rbase + i) * 4 + j] = a1[i][j];
                }
        }
        __syncthreads();

        // layer-0 gates (t = s), threads [0,32)
        if (tid < 32 && s < TLEN) {
            float zi = z_s[u0 * 4 + b0] + p0;
            float zf = z_s[(8 + u0) * 4 + b0] + p1;
            float zg = z_s[(16 + u0) * 4 + b0] + p2;
            float zo = z_s[(24 + u0) * 4 + b0] + p3;
            float ig = 1.f / (1.f + __expf(-zi));
            float fg = 1.f / (1.f + __expf(-zf));
            float gg = tanhf(zg);
            float og = 1.f / (1.f + __expf(-zo));
            float c = fg * c_s[tid] + ig * gg;
            c_s[tid] = c;
            float hval = og * tanhf(c);
            __stcg(&g_h0[(s & 1) * BSZ * H + b0 * H + col0], hval);
        }
        // layer-1 gates (t = s-1), threads [32,64)
        if (tid >= 32 && tid < 64 && s >= 1) {
            float zi = z_s[128 + u1 * 4 + b1] + gb0;
            float zf = z_s[128 + (8 + u1) * 4 + b1] + gb1;
            float zg = z_s[128 + (16 + u1) * 4 + b1] + gb2;
            float zo = z_s[128 + (24 + u1) * 4 + b1] + gb3;
            float ig = 1.f / (1.f + __expf(-zi));
            float fg = 1.f / (1.f + __expf(-zf));
            float gg = tanhf(zg);
            float og = 1.f / (1.f + __expf(-zo));
            float c = fg * c_s[tid] + ig * gg;
            c_s[tid] = c;
            float hval = og * tanhf(c);
            __stcg(&g_h1[(s & 1) * BSZ * H + b1 * H + col1], hval);
            hs1[((size_t)(b1 * TLEN + (s - 1))) * H + col1] = hval;
        }
        __syncthreads();

        grid_barrier(tid, sense);
    }

    // 1025 toggles so far (odd) -> one extra for even parity across replays
    grid_barrier(tid, sense);
}

// ---------------------------------------------------------------------------
// Host launcher (graph-capturable: kernels only, single stream)
// ---------------------------------------------------------------------------
extern "C" void kernel_launch(void* const* d_in, const int* in_sizes, int n_in,
                              void* d_out, int out_size)
{
    (void)in_sizes; (void)n_in; (void)out_size;
    const int*   x     = (const int*)  d_in[0];
    const float* emb   = (const float*)d_in[1];
    const float* Wproj = (const float*)d_in[2];
    const float* bproj = (const float*)d_in[3];
    const float* Wih0  = (const float*)d_in[4];
    const float* Whh0  = (const float*)d_in[5];
    const float* bih0  = (const float*)d_in[6];
    const float* bhh0  = (const float*)d_in[7];
    const float* Wih1  = (const float*)d_in[8];
    const float* Whh1  = (const float*)d_in[9];
    const float* bih1  = (const float*)d_in[10];
    const float* bhh1  = (const float*)d_in[11];
    float* out = (float*)d_out;

    float *act, *pre, *hs1;
    cudaGetSymbolAddress((void**)&act, g_act);
    cudaGetSymbolAddress((void**)&pre, g_pre);
    cudaGetSymbolAddress((void**)&hs1, g_hs1);

    const int RSMEM = (RPC * WPAD + 2 * BSZ * H + 256 + 64) * 4;
    cudaFuncSetAttribute(lstm_fused,
                         cudaFuncAttributeMaxDynamicSharedMemorySize, RSMEM);

    // 1) embedding
    embed_kernel<<<NTOK, 256>>>(x, emb, act);

    // 2) layer-0 input GEMM: pre = act @ Wih0^T + bih0 + bhh0
    dim3 g1(G4H / 128, NTOK / 128);
    sgemm_abt<<<g1, 256>>>(act, Wih0, bih0, bhh0, pre, NTOK, G4H, H);

    // 3) fused two-layer wavefront recurrence (subsumes pre1 GEMM)
    lstm_fused<<<NCTA_R, TPB_R, RSMEM>>>(pre, Whh0, Whh1, Wih1, bih1, bhh1, hs1);

    // 4) projection: logits = hs1 @ Wproj^T + bproj
    dim3 g2(VOCAB / 128, NTOK / 128);
    sgemm_abt<<<g2, 256>>>(hs1, Wproj, bproj, nullptr, out, NTOK, VOCAB, H);
}

// round 13
// speedup vs baseline: 1.2546x; 1.0347x over previous
#include <cuda_runtime.h>
#include <cstddef>

// Problem constants
#define H      1024
#define BSZ    4
#define TLEN   1024
#define G4H    4096          // 4*H
#define NTOK   4096          // BSZ*TLEN
#define VOCAB  32000

// Fused recurrent kernel config
#define NCTA_R 128
#define TPB_F  512           // 16 warps -> 4 warps/SMSP for latency hiding
#define UPC    8             // hidden units per CTA per layer
#define RPC    32            // gate rows per CTA per layer (4*UPC)
#define RPW    2             // rows per warp per layer (RPC / 16 warps)
#define WPAD   1028          // padded row stride for Whh0 slice in smem

// Scratch (device globals; no allocations allowed)
__device__ float g_act[(size_t)NTOK * H];
__device__ float g_pre[(size_t)NTOK * G4H];
__device__ float g_hs1[(size_t)NTOK * H];
__device__ float g_h0[2 * BSZ * H];      // layer-0 h carry, parity buffered
__device__ float g_h1[2 * BSZ * H];      // layer-1 h carry, parity buffered
__device__ int g_bar_count;              // returns to 0 every launch
__device__ int g_bar_flag;               // even # of toggles per launch -> 0

// ---------------------------------------------------------------------------
// Packed fp32x2 helpers (FFMA2) for the SGEMM
// ---------------------------------------------------------------------------
__device__ __forceinline__ unsigned long long pk2(float x, float y) {
    unsigned long long r;
    asm("mov.b64 %0, {%1, %2};" : "=l"(r) : "f"(x), "f"(y));
    return r;
}
__device__ __forceinline__ void ffma2(unsigned long long& d,
                                      unsigned long long a,
                                      unsigned long long b) {
    asm("fma.rn.f32x2 %0, %1, %2, %0;" : "+l"(d) : "l"(a), "l"(b));
}
__device__ __forceinline__ float2 upk2(unsigned long long v) {
    float2 f;
    asm("mov.b64 {%0, %1}, %2;" : "=f"(f.x), "=f"(f.y) : "l"(v));
    return f;
}

// flat grid barrier, R6-exact (acq_rel arrival, release publish, acquire poll)
__device__ __forceinline__ void grid_barrier(int tid, int& sense) {
    if (tid == 0) {
        sense ^= 1;
        int prev;
        asm volatile("atom.add.acq_rel.gpu.s32 %0, [%1], 1;"
                     : "=r"(prev) : "l"(&g_bar_count) : "memory");
        if (prev == NCTA_R - 1) {
            asm volatile("st.relaxed.gpu.s32 [%0], %1;"
                         :: "l"(&g_bar_count), "r"(0) : "memory");
            asm volatile("st.release.gpu.s32 [%0], %1;"
                         :: "l"(&g_bar_flag), "r"(sense) : "memory");
        } else {
            int f;
            do {
                asm volatile("ld.acquire.gpu.s32 %0, [%1];"
                             : "=r"(f) : "l"(&g_bar_flag) : "memory");
            } while (f != sense);
        }
    }
    __syncthreads();
}

// ---------------------------------------------------------------------------
// Embedding gather: out[n, :] = emb[x[n], :]
// ---------------------------------------------------------------------------
__global__ void embed_kernel(const int* __restrict__ x,
                             const float* __restrict__ emb,
                             float* __restrict__ out)
{
    int n = blockIdx.x;
    int tok = __ldg(&x[n]);
    const float4* src = (const float4*)(emb + (size_t)tok * H);
    float4* dst = (float4*)(out + (size_t)n * H);
    dst[threadIdx.x] = __ldg(&src[threadIdx.x]);
}

// ---------------------------------------------------------------------------
// SGEMM: C[M,N] = A[M,K] * B[N,K]^T + bias1[N] (+ bias2[N])   (R6-exact)
// ---------------------------------------------------------------------------
__global__ __launch_bounds__(256, 2)
void sgemm_abt(const float* __restrict__ A, const float* __restrict__ B,
               const float* __restrict__ bias1, const float* __restrict__ bias2,
               float* __restrict__ C, int M, int N, int K)
{
    __shared__ float As[16][132];
    __shared__ float Bs[16][132];
    const int tid = threadIdx.x;
    const int bm = blockIdx.y * 128;
    const int bn = blockIdx.x * 128;
    const int tx = tid & 15;
    const int ty = tid >> 4;
    const int lr = tid >> 2;          // 0..63
    const int lk = (tid & 3) << 2;    // 0,4,8,12

    const float* Ag = A + (size_t)(bm + lr) * K + lk;
    const float* Bg = B + (size_t)(bn + lr) * K + lk;

    unsigned long long acc2[4][8];
#pragma unroll
    for (int i = 0; i < 4; i++)
#pragma unroll
        for (int j = 0; j < 8; j++) acc2[i][j] = 0ull;

    float4 a0 = *(const float4*)(Ag);
    float4 a1 = *(const float4*)(Ag + (size_t)64 * K);
    float4 b0 = *(const float4*)(Bg);
    float4 b1 = *(const float4*)(Bg + (size_t)64 * K);

    for (int k0 = 0; k0 < K; k0 += 16) {
        __syncthreads();
        As[lk+0][lr]    = a0.x; As[lk+1][lr]    = a0.y; As[lk+2][lr]    = a0.z; As[lk+3][lr]    = a0.w;
        As[lk+0][lr+64] = a1.x; As[lk+1][lr+64] = a1.y; As[lk+2][lr+64] = a1.z; As[lk+3][lr+64] = a1.w;
        Bs[lk+0][lr]    = b0.x; Bs[lk+1][lr]    = b0.y; Bs[lk+2][lr]    = b0.z; Bs[lk+3][lr]    = b0.w;
        Bs[lk+0][lr+64] = b1.x; Bs[lk+1][lr+64] = b1.y; Bs[lk+2][lr+64] = b1.z; Bs[lk+3][lr+64] = b1.w;
        __syncthreads();
        if (k0 + 16 < K) {
            a0 = *(const float4*)(Ag + k0 + 16);
            a1 = *(const float4*)(Ag + (size_t)64 * K + k0 + 16);
            b0 = *(const float4*)(Bg + k0 + 16);
            b1 = *(const float4*)(Bg + (size_t)64 * K + k0 + 16);
        }
#pragma unroll
        for (int k = 0; k < 16; k++) {
            float4 aA = *(const float4*)&As[k][ty * 4];
            float4 aB = *(const float4*)&As[k][64 + ty * 4];
            float4 bA = *(const float4*)&Bs[k][tx * 4];
            float4 bB = *(const float4*)&Bs[k][64 + tx * 4];
            unsigned long long av2[4];
            av2[0] = pk2(aA.x, aA.y);
            av2[1] = pk2(aA.z, aA.w);
            av2[2] = pk2(aB.x, aB.y);
            av2[3] = pk2(aB.z, aB.w);
            unsigned long long bv2[8];
            bv2[0] = pk2(bA.x, bA.x);
            bv2[1] = pk2(bA.y, bA.y);
            bv2[2] = pk2(bA.z, bA.z);
            bv2[3] = pk2(bA.w, bA.w);
            bv2[4] = pk2(bB.x, bB.x);
            bv2[5] = pk2(bB.y, bB.y);
            bv2[6] = pk2(bB.z, bB.z);
            bv2[7] = pk2(bB.w, bB.w);
#pragma unroll
            for (int i = 0; i < 4; i++)
#pragma unroll
                for (int j = 0; j < 8; j++)
                    ffma2(acc2[i][j], av2[i], bv2[j]);
        }
    }

    float acc[8][8];
#pragma unroll
    for (int i2 = 0; i2 < 4; i2++)
#pragma unroll
        for (int j = 0; j < 8; j++) {
            float2 v = upk2(acc2[i2][j]);
            acc[2 * i2][j]     = v.x;
            acc[2 * i2 + 1][j] = v.y;
        }

    float bb[8];
#pragma unroll
    for (int jh = 0; jh < 2; jh++)
#pragma unroll
        for (int j = 0; j < 4; j++) {
            int n = bn + jh * 64 + tx * 4 + j;
            float v = bias1 ? __ldg(&bias1[n]) : 0.f;
            if (bias2) v += __ldg(&bias2[n]);
            bb[jh * 4 + j] = v;
        }
#pragma unroll
    for (int ih = 0; ih < 2; ih++)
#pragma unroll
        for (int i = 0; i < 4; i++) {
            int m = bm + ih * 64 + ty * 4 + i;
#pragma unroll
            for (int jh = 0; jh < 2; jh++) {
                float4 v;
                v.x = acc[ih*4+i][jh*4+0] + bb[jh*4+0];
                v.y = acc[ih*4+i][jh*4+1] + bb[jh*4+1];
                v.z = acc[ih*4+i][jh*4+2] + bb[jh*4+2];
                v.w = acc[ih*4+i][jh*4+3] + bb[jh*4+3];
                *(float4*)&C[(size_t)m * N + bn + jh * 64 + tx * 4] = v;
            }
        }
}

// ---------------------------------------------------------------------------
// Fused two-layer wavefront LSTM, 512 threads (16 warps = 4/SMSP).
// CTA owns 8 hidden units of BOTH layers; warp owns 2 gate rows per layer.
// Superstep s: layer-0 step t=s (Whh0 SMEM-resident) AND layer-1 step t=s-1
// (Whh1 + Wih1 streamed from L2 via __ldcg — subsumes the pre1 GEMM).
// One grid barrier per superstep (1026 total, even). h carries parity-
// double-buffered. Per-row lane->k partition identical to R12 (bitwise-same
// reductions).
// ---------------------------------------------------------------------------
__global__ __launch_bounds__(TPB_F, 1)
void lstm_fused(const float* __restrict__ pre0,
                const float* __restrict__ Whh0,
                const float* __restrict__ Whh1,
                const float* __restrict__ Wih1,
                const float* __restrict__ bih1,
                const float* __restrict__ bhh1,
                float* __restrict__ hs1)
{
    extern __shared__ float sm[];
    float* whh0_s = sm;                        // RPC * WPAD
    float* h0_s   = whh0_s + RPC * WPAD;       // BSZ * H
    float* h1_s   = h0_s + BSZ * H;            // BSZ * H
    float* z_s    = h1_s + BSZ * H;            // 256 (layer0: 0..127, layer1: 128..255)
    float* c_s    = z_s + 256;                 // 64  (layer0: 0..31,  layer1: 32..63)

    const int tid  = threadIdx.x;
    const int cta  = blockIdx.x;
    const int warp = tid >> 5;
    const int lane = tid & 31;

    // Whh0 slice into smem: local row r = q*8+uu -> global row q*H + cta*8 + uu
    for (int i = tid; i < RPC * H; i += TPB_F) {
        int r = i >> 10;
        int k = i & (H - 1);
        int grow = (r >> 3) * H + cta * UPC + (r & 7);
        whh0_s[r * WPAD + k] = __ldg(&Whh0[(size_t)grow * H + k]);
    }
    if (tid < 64) c_s[tid] = 0.f;

    // layer-1 gate biases (constant): thread tid in [32,64) handles (u1, b1)
    float gb0 = 0.f, gb1 = 0.f, gb2 = 0.f, gb3 = 0.f;
    int u1 = 0, b1 = 0, col1 = 0;
    if (tid >= 32 && tid < 64) {
        u1 = (tid - 32) >> 2;
        b1 = (tid - 32) & 3;
        col1 = cta * UPC + u1;
        gb0 = __ldg(&bih1[col1])         + __ldg(&bhh1[col1]);
        gb1 = __ldg(&bih1[H + col1])     + __ldg(&bhh1[H + col1]);
        gb2 = __ldg(&bih1[2 * H + col1]) + __ldg(&bhh1[2 * H + col1]);
        gb3 = __ldg(&bih1[3 * H + col1]) + __ldg(&bhh1[3 * H + col1]);
    }
    // layer-0 gate mapping: tid in [0,32)
    int u0 = 0, b0 = 0, col0 = 0;
    if (tid < 32) {
        u0 = tid >> 2;
        b0 = tid & 3;
        col0 = cta * UPC + u0;
    }

    // layer-1 streamed weight row pointers for this warp's RPW rows
    const int rbase = warp * RPW;
    const float* wh1p[RPW];
    const float* wi1p[RPW];
#pragma unroll
    for (int i = 0; i < RPW; i++) {
        int r = rbase + i;
        size_t grow = (size_t)((r >> 3) * H + cta * UPC + (r & 7));
        wh1p[i] = Whh1 + grow * H;
        wi1p[i] = Wih1 + grow * H;
    }

    int sense = 0;
    __syncthreads();

    for (int s = 0; s <= TLEN; s++) {
        // stage h0(s-1) and h1(s-2) into smem from parity buffer (s-1)&1
        {
            float4* d0 = (float4*)h0_s;
            float4* d1 = (float4*)h1_s;
            if (s == 0) {
                for (int i = tid; i < (BSZ * H) / 4; i += TPB_F) {
                    d0[i] = make_float4(0.f, 0.f, 0.f, 0.f);
                    d1[i] = make_float4(0.f, 0.f, 0.f, 0.f);
                }
            } else {
                const float4* s0 = (const float4*)(g_h0 + ((s - 1) & 1) * BSZ * H);
                for (int i = tid; i < (BSZ * H) / 4; i += TPB_F)
                    d0[i] = __ldcg(s0 + i);
                if (s == 1) {
                    for (int i = tid; i < (BSZ * H) / 4; i += TPB_F)
                        d1[i] = make_float4(0.f, 0.f, 0.f, 0.f);
                } else {
                    const float4* s1 = (const float4*)(g_h1 + ((s - 1) & 1) * BSZ * H);
                    for (int i = tid; i < (BSZ * H) / 4; i += TPB_F)
                        d1[i] = __ldcg(s1 + i);
                }
            }
        }
        // prefetch layer-0 pre-activations (t = s), gate threads only
        float p0 = 0.f, p1 = 0.f, p2 = 0.f, p3 = 0.f;
        if (tid < 32 && s < TLEN) {
            size_t base = ((size_t)(b0 * TLEN + s)) * G4H + cta * UPC + u0;
            p0 = __ldg(&pre0[base]);
            p1 = __ldg(&pre0[base + H]);
            p2 = __ldg(&pre0[base + 2 * H]);
            p3 = __ldg(&pre0[base + 3 * H]);
        }
        __syncthreads();

        // dots: a0 = Whh0_s . h0s ; a1 = Whh1 . h1s + Wih1 . h0s (streamed)
        float a0[RPW][4], a1[RPW][4];
#pragma unroll
        for (int i = 0; i < RPW; i++)
#pragma unroll
            for (int j = 0; j < 4; j++) { a0[i][j] = 0.f; a1[i][j] = 0.f; }

#pragma unroll
        for (int p = 0; p < 8; p++) {
            int k = p * 128 + lane * 4;
            float4 x0 = *(const float4*)&h0_s[k];
            float4 x1 = *(const float4*)&h0_s[H + k];
            float4 x2 = *(const float4*)&h0_s[2 * H + k];
            float4 x3 = *(const float4*)&h0_s[3 * H + k];
            float4 y0 = *(const float4*)&h1_s[k];
            float4 y1 = *(const float4*)&h1_s[H + k];
            float4 y2 = *(const float4*)&h1_s[2 * H + k];
            float4 y3 = *(const float4*)&h1_s[3 * H + k];
#pragma unroll
            for (int i = 0; i < RPW; i++) {
                float4 w0 = *(const float4*)&whh0_s[(rbase + i) * WPAD + k];
                a0[i][0] += w0.x*x0.x + w0.y*x0.y + w0.z*x0.z + w0.w*x0.w;
                a0[i][1] += w0.x*x1.x + w0.y*x1.y + w0.z*x1.z + w0.w*x1.w;
                a0[i][2] += w0.x*x2.x + w0.y*x2.y + w0.z*x2.z + w0.w*x2.w;
                a0[i][3] += w0.x*x3.x + w0.y*x3.y + w0.z*x3.z + w0.w*x3.w;
                float4 wa = __ldcg((const float4*)(wh1p[i] + k));
                float4 wb = __ldcg((const float4*)(wi1p[i] + k));
                a1[i][0] += wa.x*y0.x + wa.y*y0.y + wa.z*y0.z + wa.w*y0.w
                          + wb.x*x0.x + wb.y*x0.y + wb.z*x0.z + wb.w*x0.w;
                a1[i][1] += wa.x*y1.x + wa.y*y1.y + wa.z*y1.z + wa.w*y1.w
                          + wb.x*x1.x + wb.y*x1.y + wb.z*x1.z + wb.w*x1.w;
                a1[i][2] += wa.x*y2.x + wa.y*y2.y + wa.z*y2.z + wa.w*y2.w
                          + wb.x*x2.x + wb.y*x2.y + wb.z*x2.z + wb.w*x2.w;
                a1[i][3] += wa.x*y3.x + wa.y*y3.y + wa.z*y3.z + wa.w*y3.w
                          + wb.x*x3.x + wb.y*x3.y + wb.z*x3.z + wb.w*x3.w;
            }
        }
        // warp reductions
#pragma unroll
        for (int i = 0; i < RPW; i++)
#pragma unroll
            for (int j = 0; j < 4; j++) {
                float v = a0[i][j];
                v += __shfl_xor_sync(0xffffffffu, v, 16);
                v += __shfl_xor_sync(0xffffffffu, v, 8);
                v += __shfl_xor_sync(0xffffffffu, v, 4);
                v += __shfl_xor_sync(0xffffffffu, v, 2);
                v += __shfl_xor_sync(0xffffffffu, v, 1);
                a0[i][j] = v;
                float w = a1[i][j];
                w += __shfl_xor_sync(0xffffffffu, w, 16);
                w += __shfl_xor_sync(0xffffffffu, w, 8);
                w += __shfl_xor_sync(0xffffffffu, w, 4);
                w += __shfl_xor_sync(0xffffffffu, w, 2);
                w += __shfl_xor_sync(0xffffffffu, w, 1);
                a1[i][j] = w;
            }
        if (lane == 0) {
#pragma unroll
            for (int i = 0; i < RPW; i++)
#pragma unroll
                for (int j = 0; j < 4; j++) {
                    z_s[(rbase + i) * 4 + j]       = a0[i][j];
                    z_s[128 + (rbase + i) * 4 + j] = a1[i][j];
                }
        }
        __syncthreads();

        // layer-0 gates (t = s), threads [0,32)
        if (tid < 32 && s < TLEN) {
            float zi = z_s[u0 * 4 + b0] + p0;
            float zf = z_s[(8 + u0) * 4 + b0] + p1;
            float zg = z_s[(16 + u0) * 4 + b0] + p2;
            float zo = z_s[(24 + u0) * 4 + b0] + p3;
            float ig = 1.f / (1.f + __expf(-zi));
            float fg = 1.f / (1.f + __expf(-zf));
            float gg = tanhf(zg);
            float og = 1.f / (1.f + __expf(-zo));
            float c = fg * c_s[tid] + ig * gg;
            c_s[tid] = c;
            float hval = og * tanhf(c);
            __stcg(&g_h0[(s & 1) * BSZ * H + b0 * H + col0], hval);
        }
        // layer-1 gates (t = s-1), threads [32,64)
        if (tid >= 32 && tid < 64 && s >= 1) {
            float zi = z_s[128 + u1 * 4 + b1] + gb0;
            float zf = z_s[128 + (8 + u1) * 4 + b1] + gb1;
            float zg = z_s[128 + (16 + u1) * 4 + b1] + gb2;
            float zo = z_s[128 + (24 + u1) * 4 + b1] + gb3;
            float ig = 1.f / (1.f + __expf(-zi));
            float fg = 1.f / (1.f + __expf(-zf));
            float gg = tanhf(zg);
            float og = 1.f / (1.f + __expf(-zo));
            float c = fg * c_s[tid] + ig * gg;
            c_s[tid] = c;
            float hval = og * tanhf(c);
            __stcg(&g_h1[(s & 1) * BSZ * H + b1 * H + col1], hval);
            hs1[((size_t)(b1 * TLEN + (s - 1))) * H + col1] = hval;
        }
        __syncthreads();

        grid_barrier(tid, sense);
    }

    // 1025 toggles so far (odd) -> one extra for even parity across replays
    grid_barrier(tid, sense);
}

// ---------------------------------------------------------------------------
// Host launcher (graph-capturable: kernels only, single stream)
// ---------------------------------------------------------------------------
extern "C" void kernel_launch(void* const* d_in, const int* in_sizes, int n_in,
                              void* d_out, int out_size)
{
    (void)in_sizes; (void)n_in; (void)out_size;
    const int*   x     = (const int*)  d_in[0];
    const float* emb   = (const float*)d_in[1];
    const float* Wproj = (const float*)d_in[2];
    const float* bproj = (const float*)d_in[3];
    const float* Wih0  = (const float*)d_in[4];
    const float* Whh0  = (const float*)d_in[5];
    const float* bih0  = (const float*)d_in[6];
    const float* bhh0  = (const float*)d_in[7];
    const float* Wih1  = (const float*)d_in[8];
    const float* Whh1  = (const float*)d_in[9];
    const float* bih1  = (const float*)d_in[10];
    const float* bhh1  = (const float*)d_in[11];
    float* out = (float*)d_out;

    float *act, *pre, *hs1;
    cudaGetSymbolAddress((void**)&act, g_act);
    cudaGetSymbolAddress((void**)&pre, g_pre);
    cudaGetSymbolAddress((void**)&hs1, g_hs1);

    const int RSMEM = (RPC * WPAD + 2 * BSZ * H + 256 + 64) * 4;
    cudaFuncSetAttribute(lstm_fused,
                         cudaFuncAttributeMaxDynamicSharedMemorySize, RSMEM);

    // 1) embedding
    embed_kernel<<<NTOK, 256>>>(x, emb, act);

    // 2) layer-0 input GEMM: pre = act @ Wih0^T + bih0 + bhh0
    dim3 g1(G4H / 128, NTOK / 128);
    sgemm_abt<<<g1, 256>>>(act, Wih0, bih0, bhh0, pre, NTOK, G4H, H);

    // 3) fused two-layer wavefront recurrence (subsumes pre1 GEMM)
    lstm_fused<<<NCTA_R, TPB_F, RSMEM>>>(pre, Whh0, Whh1, Wih1, bih1, bhh1, hs1);

    // 4) projection: logits = hs1 @ Wproj^T + bproj
    dim3 g2(VOCAB / 128, NTOK / 128);
    sgemm_abt<<<g2, 256>>>(hs1, Wproj, bproj, nullptr, out, NTOK, VOCAB, H);
}